// round 11
// baseline (speedup 1.0000x reference)
#include <cuda_runtime.h>
#include <math.h>

// Problem constants
#define T_STEPS 12
#define NV      10000
#define DIN     256
#define HID     512
#define H3      1536            // 3*HID
#define NE      160000
#define NCONV   2

// -------------------- scratch (device globals; no allocation) --------------------
__device__ __align__(16) float g_h0[NV * HID];     // hidden state (ping)
__device__ __align__(16) float g_h1[NV * HID];     // hidden state (pong)
__device__ __align__(16) float g_hW[NV * HID];     // h @ conv_W
__device__ __align__(16) float g_deg  [NV];
__device__ __align__(16) float g_dinv [NV];
__device__ __align__(16) float g_selfw[NV];
__device__ __align__(16) float g_norm [NE];
__device__ __align__(16) int   g_count[NV];
__device__ __align__(16) int   g_start[NV + 1];
__device__ __align__(16) int   g_wptr [NV];
__device__ __align__(16) int   g_csr_src[NE];
__device__ __align__(16) float g_csr_w  [NE];
__device__            int   g_idx64;               // 1 if edge_index is int64

__device__ __forceinline__ float* hbuf(int p) { return p ? g_h1 : g_h0; }

// Load edge_index element `pos` (element index, not byte), either dtype.
__device__ __forceinline__ int load_idx(const void* ei, int pos) {
    if (g_idx64) return (int)((const long long*)ei)[pos];
    return ((const int*)ei)[pos];
}

// -------------------- dtype detection --------------------
// int64 little-endian values < 2^32: every odd int32 word is 0.
// int32 node indices in [0,10000): odd words nonzero w.p. ~1-1e-4 each.
__global__ void detect_kernel(const int* __restrict__ ei32) {
    if (threadIdx.x == 0) {
        int is64 = 1;
        #pragma unroll
        for (int k = 1; k < 64; k += 2)
            if (ei32[k] != 0) { is64 = 0; break; }
        g_idx64 = is64;
    }
}

// -------------------- preprocessing kernels --------------------

__global__ void init_kernel() {
    int i = blockIdx.x * blockDim.x + threadIdx.x;
    int total = NV * HID;
    for (int idx = i; idx < total; idx += gridDim.x * blockDim.x) {
        g_h0[idx] = 0.0f;
        if (idx < NV) { g_deg[idx] = 0.0f; g_count[idx] = 0; }
    }
}

__global__ void deg_count_kernel(const void* __restrict__ ei,
                                 const float* __restrict__ ew) {
    int e = blockIdx.x * blockDim.x + threadIdx.x;
    if (e >= NE) return;
    int c = load_idx(ei, NE + e);
    atomicAdd(&g_deg[c], ew[e]);
    atomicAdd(&g_count[c], 1);
}

__global__ void dinv_kernel() {
    int n = blockIdx.x * blockDim.x + threadIdx.x;
    if (n >= NV) return;
    float d = rsqrtf(g_deg[n] + 1.0f);
    g_dinv[n]  = d;
    g_selfw[n] = d * d;
}

__global__ void norm_kernel(const void* __restrict__ ei,
                            const float* __restrict__ ew) {
    int e = blockIdx.x * blockDim.x + threadIdx.x;
    if (e >= NE) return;
    int r = load_idx(ei, e);
    int c = load_idx(ei, NE + e);
    g_norm[e] = g_dinv[r] * ew[e] * g_dinv[c];
}

// single-block exclusive scan over g_count -> g_start (also seeds g_wptr)
__global__ void scan_kernel() {
    __shared__ int sh[1024];
    __shared__ int carry;
    if (threadIdx.x == 0) carry = 0;
    __syncthreads();
    for (int base = 0; base < NV; base += 1024) {
        int i = base + threadIdx.x;
        int v = (i < NV) ? g_count[i] : 0;
        sh[threadIdx.x] = v;
        __syncthreads();
        for (int off = 1; off < 1024; off <<= 1) {
            int t = (threadIdx.x >= off) ? sh[threadIdx.x - off] : 0;
            __syncthreads();
            sh[threadIdx.x] += t;
            __syncthreads();
        }
        if (i < NV) {
            int excl = carry + sh[threadIdx.x] - v;
            g_start[i] = excl;
            g_wptr[i]  = excl;
        }
        __syncthreads();
        if (threadIdx.x == 0) carry += sh[1023];
        __syncthreads();
    }
    if (threadIdx.x == 0) g_start[NV] = carry;
}

__global__ void fill_kernel(const void* __restrict__ ei) {
    int e = blockIdx.x * blockDim.x + threadIdx.x;
    if (e >= NE) return;
    int c = load_idx(ei, NE + e);
    int pos = atomicAdd(&g_wptr[c], 1);
    g_csr_src[pos] = load_idx(ei, e);
    g_csr_w[pos]   = g_norm[e];
}

// -------------------- fused GRU: h_out = GRUCell(x, h_in) --------------------
// Gates = [x | h_in] @ [W_ih | W_hh]^T in one two-phase GEMM; epilogue applies
// the GRU nonlinearity and writes h_out directly (no gate scratch buffers).
// Block tile: 64 nodes x 128 h-cols (x3 gates). 256 threads, thread tile 4x8.
#define GBM 64
#define GBN 128
#define GBK 16

__device__ __forceinline__ float sigm(float x) { return 1.0f / (1.0f + expf(-x)); }

__global__ void __launch_bounds__(256)
gru_fused_kernel(const float* __restrict__ xs,
                 const float* __restrict__ W_ih,
                 const float* __restrict__ W_hh,
                 const float* __restrict__ b_ih,
                 const float* __restrict__ b_hh,
                 int t, int p) {
    const float* x     = xs + (size_t)t * NV * DIN;
    const float* h_in  = hbuf(p);
    float*       h_out = hbuf(p ^ 1);

    __shared__ float As[GBK][GBM];        // 16 x 64
    __shared__ float Bs[3][GBK][GBN];     // 3 x 16 x 128

    int tid = threadIdx.x;
    int tx = tid & 15;          // 16 col groups of 8
    int ty = tid >> 4;          // 16 row groups of 4
    int row0 = blockIdx.y * GBM;
    int col0 = blockIdx.x * GBN;          // h-col base in [0, 512)

    float aR[4][8], aZ[4][8], aNi[4][8], aNh[4][8];
    #pragma unroll
    for (int i = 0; i < 4; i++)
        #pragma unroll
        for (int j = 0; j < 8; j++) { aR[i][j]=0.f; aZ[i][j]=0.f; aNi[i][j]=0.f; aNh[i][j]=0.f; }

    // ---- phase 1: K over x (DIN=256), n accumulates into aNi ----
    #pragma unroll 1
    for (int k0 = 0; k0 < DIN; k0 += GBK) {
        {   // A tile: 64 rows x 16 k (transposed)
            int r = tid >> 2, c4 = (tid & 3) * 4;
            float4 v = make_float4(0.f,0.f,0.f,0.f);
            int gr = row0 + r;
            if (gr < NV) v = *reinterpret_cast<const float4*>(&x[(size_t)gr * DIN + k0 + c4]);
            As[c4+0][r]=v.x; As[c4+1][r]=v.y; As[c4+2][r]=v.z; As[c4+3][r]=v.w;
        }
        #pragma unroll
        for (int i = 0; i < 6; i++) {   // B tiles: 3 gates x 128 cols x 16 k
            int s = tid + i * 256;
            int g = s >> 9, rem = s & 511;
            int c = rem >> 2, c4 = (rem & 3) * 4;
            int wrow = g * HID + col0 + c;
            float4 v = *reinterpret_cast<const float4*>(&W_ih[(size_t)wrow * DIN + k0 + c4]);
            Bs[g][c4+0][c]=v.x; Bs[g][c4+1][c]=v.y; Bs[g][c4+2][c]=v.z; Bs[g][c4+3][c]=v.w;
        }
        __syncthreads();
        #pragma unroll
        for (int k = 0; k < GBK; k++) {
            float a[4], br[8], bz[8], bn[8];
            *reinterpret_cast<float4*>(a) = *reinterpret_cast<float4*>(&As[k][ty*4]);
            *reinterpret_cast<float4*>(&br[0]) = *reinterpret_cast<float4*>(&Bs[0][k][tx*8]);
            *reinterpret_cast<float4*>(&br[4]) = *reinterpret_cast<float4*>(&Bs[0][k][tx*8+4]);
            *reinterpret_cast<float4*>(&bz[0]) = *reinterpret_cast<float4*>(&Bs[1][k][tx*8]);
            *reinterpret_cast<float4*>(&bz[4]) = *reinterpret_cast<float4*>(&Bs[1][k][tx*8+4]);
            *reinterpret_cast<float4*>(&bn[0]) = *reinterpret_cast<float4*>(&Bs[2][k][tx*8]);
            *reinterpret_cast<float4*>(&bn[4]) = *reinterpret_cast<float4*>(&Bs[2][k][tx*8+4]);
            #pragma unroll
            for (int i = 0; i < 4; i++)
                #pragma unroll
                for (int j = 0; j < 8; j++) {
                    aR [i][j] = fmaf(a[i], br[j], aR [i][j]);
                    aZ [i][j] = fmaf(a[i], bz[j], aZ [i][j]);
                    aNi[i][j] = fmaf(a[i], bn[j], aNi[i][j]);
                }
        }
        __syncthreads();
    }

    // ---- phase 2: K over h_in (HID=512), n accumulates into aNh ----
    #pragma unroll 1
    for (int k0 = 0; k0 < HID; k0 += GBK) {
        {
            int r = tid >> 2, c4 = (tid & 3) * 4;
            float4 v = make_float4(0.f,0.f,0.f,0.f);
            int gr = row0 + r;
            if (gr < NV) v = *reinterpret_cast<const float4*>(&h_in[(size_t)gr * HID + k0 + c4]);
            As[c4+0][r]=v.x; As[c4+1][r]=v.y; As[c4+2][r]=v.z; As[c4+3][r]=v.w;
        }
        #pragma unroll
        for (int i = 0; i < 6; i++) {
            int s = tid + i * 256;
            int g = s >> 9, rem = s & 511;
            int c = rem >> 2, c4 = (rem & 3) * 4;
            int wrow = g * HID + col0 + c;
            float4 v = *reinterpret_cast<const float4*>(&W_hh[(size_t)wrow * HID + k0 + c4]);
            Bs[g][c4+0][c]=v.x; Bs[g][c4+1][c]=v.y; Bs[g][c4+2][c]=v.z; Bs[g][c4+3][c]=v.w;
        }
        __syncthreads();
        #pragma unroll
        for (int k = 0; k < GBK; k++) {
            float a[4], br[8], bz[8], bn[8];
            *reinterpret_cast<float4*>(a) = *reinterpret_cast<float4*>(&As[k][ty*4]);
            *reinterpret_cast<float4*>(&br[0]) = *reinterpret_cast<float4*>(&Bs[0][k][tx*8]);
            *reinterpret_cast<float4*>(&br[4]) = *reinterpret_cast<float4*>(&Bs[0][k][tx*8+4]);
            *reinterpret_cast<float4*>(&bz[0]) = *reinterpret_cast<float4*>(&Bs[1][k][tx*8]);
            *reinterpret_cast<float4*>(&bz[4]) = *reinterpret_cast<float4*>(&Bs[1][k][tx*8+4]);
            *reinterpret_cast<float4*>(&bn[0]) = *reinterpret_cast<float4*>(&Bs[2][k][tx*8]);
            *reinterpret_cast<float4*>(&bn[4]) = *reinterpret_cast<float4*>(&Bs[2][k][tx*8+4]);
            #pragma unroll
            for (int i = 0; i < 4; i++)
                #pragma unroll
                for (int j = 0; j < 8; j++) {
                    aR [i][j] = fmaf(a[i], br[j], aR [i][j]);
                    aZ [i][j] = fmaf(a[i], bz[j], aZ [i][j]);
                    aNh[i][j] = fmaf(a[i], bn[j], aNh[i][j]);
                }
        }
        __syncthreads();
    }

    // ---- epilogue: GRU nonlinearity, write h_out ----
    float brz[8], bzz[8], bin_[8], bhn[8];
    #pragma unroll
    for (int j = 0; j < 8; j++) {
        int gc = col0 + tx * 8 + j;
        brz[j]  = b_ih[gc]            + b_hh[gc];
        bzz[j]  = b_ih[HID + gc]      + b_hh[HID + gc];
        bin_[j] = b_ih[2 * HID + gc];
        bhn[j]  = b_hh[2 * HID + gc];
    }
    #pragma unroll
    for (int i = 0; i < 4; i++) {
        int gr = row0 + ty * 4 + i;
        if (gr >= NV) continue;
        #pragma unroll
        for (int j = 0; j < 8; j++) {
            int gc = col0 + tx * 8 + j;
            float r = sigm(aR[i][j] + brz[j]);
            float z = sigm(aZ[i][j] + bzz[j]);
            float n = tanhf(aNi[i][j] + bin_[j] + r * (aNh[i][j] + bhn[j]));
            float ho = h_in[(size_t)gr * HID + gc];
            h_out[(size_t)gr * HID + gc] = (1.0f - z) * n + z * ho;
        }
    }
}

// -------------------- conv SGEMM: hW = h * conv_W[l]  (128x128 tiles) --------------------
__global__ void __launch_bounds__(256, 2)
gemm_cv_kernel(const float* __restrict__ conv_W, int l, int hp) {
    const float* A = hbuf(hp);
    const float* B = conv_W + (size_t)l * HID * HID;
    float*       C = g_hW;

    __shared__ float As[16][128];
    __shared__ float Bs[16][128];
    int tid = threadIdx.x;
    int tx = tid & 15, ty = tid >> 4;
    int row0 = blockIdx.y * 128;
    int col0 = blockIdx.x * 128;

    float acc[8][8];
    #pragma unroll
    for (int i = 0; i < 8; i++)
        #pragma unroll
        for (int j = 0; j < 8; j++) acc[i][j] = 0.0f;

    #pragma unroll 1
    for (int k0 = 0; k0 < HID; k0 += 16) {
        #pragma unroll
        for (int i = 0; i < 2; i++) {
            int f = tid + i * 256;
            int r = f >> 2, c4 = (f & 3) * 4;
            float4 v = make_float4(0.f, 0.f, 0.f, 0.f);
            int gr = row0 + r;
            if (gr < NV)
                v = *reinterpret_cast<const float4*>(&A[(size_t)gr * HID + k0 + c4]);
            As[c4 + 0][r] = v.x; As[c4 + 1][r] = v.y;
            As[c4 + 2][r] = v.z; As[c4 + 3][r] = v.w;
        }
        #pragma unroll
        for (int i = 0; i < 2; i++) {
            int f = tid + i * 256;
            int kr = f >> 5, c = (f & 31) * 4;
            float4 v = *reinterpret_cast<const float4*>(
                &B[(size_t)(k0 + kr) * HID + col0 + c]);
            *reinterpret_cast<float4*>(&Bs[kr][c]) = v;
        }
        __syncthreads();

        #pragma unroll
        for (int k = 0; k < 16; k++) {
            float a[8], b[8];
            *reinterpret_cast<float4*>(&a[0]) = *reinterpret_cast<float4*>(&As[k][ty * 8]);
            *reinterpret_cast<float4*>(&a[4]) = *reinterpret_cast<float4*>(&As[k][ty * 8 + 4]);
            *reinterpret_cast<float4*>(&b[0]) = *reinterpret_cast<float4*>(&Bs[k][tx * 8]);
            *reinterpret_cast<float4*>(&b[4]) = *reinterpret_cast<float4*>(&Bs[k][tx * 8 + 4]);
            #pragma unroll
            for (int i = 0; i < 8; i++)
                #pragma unroll
                for (int j = 0; j < 8; j++)
                    acc[i][j] = fmaf(a[i], b[j], acc[i][j]);
        }
        __syncthreads();
    }

    #pragma unroll
    for (int i = 0; i < 8; i++) {
        int gr = row0 + ty * 8 + i;
        if (gr < NV) {
            float4 v0 = make_float4(acc[i][0], acc[i][1], acc[i][2], acc[i][3]);
            float4 v1 = make_float4(acc[i][4], acc[i][5], acc[i][6], acc[i][7]);
            *reinterpret_cast<float4*>(&C[(size_t)gr * HID + col0 + tx * 8])     = v0;
            *reinterpret_cast<float4*>(&C[(size_t)gr * HID + col0 + tx * 8 + 4]) = v1;
        }
    }
}

// -------------------- GCN aggregation: h = relu(agg + selfw*hW + b) --------------------
__global__ void agg_kernel(const float* __restrict__ conv_b, int l, int hp) {
    int n = blockIdx.x;            // node
    int j = threadIdx.x;           // 0..127 float4 column
    const float4* hw4 = reinterpret_cast<const float4*>(g_hW);
    const float*  bch = conv_b + (size_t)l * HID;
    float*        h   = hbuf(hp);

    float4 acc = make_float4(0.f, 0.f, 0.f, 0.f);
    int s = g_start[n], e = g_start[n + 1];
    for (int p = s; p < e; p++) {
        int   src = g_csr_src[p];
        float w   = g_csr_w[p];
        float4 v = __ldg(&hw4[(size_t)src * 128 + j]);
        acc.x = fmaf(w, v.x, acc.x);
        acc.y = fmaf(w, v.y, acc.y);
        acc.z = fmaf(w, v.z, acc.z);
        acc.w = fmaf(w, v.w, acc.w);
    }
    float sw = g_selfw[n];
    float4 hv = hw4[(size_t)n * 128 + j];
    float4 b  = reinterpret_cast<const float4*>(bch)[j];
    float4 r;
    r.x = fmaxf(acc.x + sw * hv.x + b.x, 0.0f);
    r.y = fmaxf(acc.y + sw * hv.y + b.y, 0.0f);
    r.z = fmaxf(acc.z + sw * hv.z + b.z, 0.0f);
    r.w = fmaxf(acc.w + sw * hv.w + b.w, 0.0f);
    reinterpret_cast<float4*>(h)[(size_t)n * 128 + j] = r;
}

// -------------------- final linear: out[n] = h[n,:] . lin_W + lin_b --------------------
__global__ void lin_kernel(const float* __restrict__ lin_W,
                           const float* __restrict__ lin_b,
                           float* __restrict__ out, int t, int hp) {
    const float* h = hbuf(hp);
    int warp = (blockIdx.x * blockDim.x + threadIdx.x) >> 5;
    int lane = threadIdx.x & 31;
    if (warp >= NV) return;
    float s = 0.0f;
    for (int j = lane; j < HID; j += 32)
        s = fmaf(h[(size_t)warp * HID + j], lin_W[j], s);
    #pragma unroll
    for (int o = 16; o > 0; o >>= 1) s += __shfl_down_sync(0xFFFFFFFFu, s, o);
    if (lane == 0) out[(size_t)t * NV + warp] = s + lin_b[0];
}

// -------------------- host orchestration: kernel launches ONLY --------------------
extern "C" void kernel_launch(void* const* d_in, const int* in_sizes, int n_in,
                              void* d_out, int out_size) {
    const float* xs     = (const float*)d_in[0];
    const void*  ei     = d_in[1];                 // int32 OR int64 (detected)
    const float* ew     = (const float*)d_in[2];
    const float* W_ih   = (const float*)d_in[3];
    const float* W_hh   = (const float*)d_in[4];
    const float* b_ih   = (const float*)d_in[5];
    const float* b_hh   = (const float*)d_in[6];
    const float* conv_W = (const float*)d_in[7];
    const float* conv_b = (const float*)d_in[8];
    const float* lin_W  = (const float*)d_in[9];
    const float* lin_b  = (const float*)d_in[10];
    float* out = (float*)d_out;

    // preprocessing
    detect_kernel<<<1, 32>>>((const int*)ei);
    init_kernel<<<592, 256>>>();
    deg_count_kernel<<<(NE + 255) / 256, 256>>>(ei, ew);
    dinv_kernel<<<(NV + 255) / 256, 256>>>();
    norm_kernel<<<(NE + 255) / 256, 256>>>(ei, ew);
    scan_kernel<<<1, 1024>>>();
    fill_kernel<<<(NE + 255) / 256, 256>>>(ei);

    dim3 grid_gru(HID / GBN, (NV + GBM - 1) / GBM);    // 4 x 157
    dim3 grid_cv(HID / 128, (NV + 127) / 128);         // 4 x 79

    for (int t = 0; t < T_STEPS; t++) {
        int p = t & 1;            // h_in = hbuf(p); conv/agg/lin buffer = hbuf(p^1)
        gru_fused_kernel<<<grid_gru, 256>>>(xs, W_ih, W_hh, b_ih, b_hh, t, p);
        for (int l = 0; l < NCONV; l++) {
            gemm_cv_kernel<<<grid_cv, 256>>>(conv_W, l, p ^ 1);
            agg_kernel<<<NV, 128>>>(conv_b, l, p ^ 1);
        }
        lin_kernel<<<(NV * 32 + 255) / 256, 256>>>(lin_W, lin_b, out, t, p ^ 1);
    }
}

// round 14
// speedup vs baseline: 2.2945x; 2.2945x over previous
#include <cuda_runtime.h>
#include <cuda_bf16.h>
#include <math.h>
#include <stdint.h>

// Problem constants
#define T_STEPS 12
#define NV      10000
#define DIN     256
#define HID     512
#define H3      1536            // 3*HID
#define NE      160000
#define NCONV   2

// -------------------- scratch (device globals; no allocation) --------------------
__device__ __align__(16) float g_GI[NV * H3];      // x @ W_ih^T
__device__ __align__(16) float g_GH[NV * H3];      // h @ W_hh^T
__device__ __align__(16) float g_h0[NV * HID];     // hidden state (ping)
__device__ __align__(16) float g_h1[NV * HID];     // hidden state (pong)
__device__ __align__(16) float g_hW[NV * HID];     // h @ conv_W
__device__ __align__(16) float g_deg  [NV];
__device__ __align__(16) float g_dinv [NV];
__device__ __align__(16) float g_selfw[NV];
__device__ __align__(16) float g_norm [NE];
__device__ __align__(16) int   g_count[NV];
__device__ __align__(16) int   g_start[NV + 1];
__device__ __align__(16) int   g_wptr [NV];
__device__ __align__(16) int   g_csr_src[NE];
__device__ __align__(16) float g_csr_w  [NE];
__device__            int   g_idx64;               // 1 if edge_index is int64

__device__ __forceinline__ float* hbuf(int p) { return p ? g_h1 : g_h0; }

__device__ __forceinline__ int load_idx(const void* ei, int pos) {
    if (g_idx64) return (int)((const long long*)ei)[pos];
    return ((const int*)ei)[pos];
}

// -------------------- dtype detection --------------------
__global__ void detect_kernel(const int* __restrict__ ei32) {
    if (threadIdx.x == 0) {
        int is64 = 1;
        #pragma unroll
        for (int k = 1; k < 64; k += 2)
            if (ei32[k] != 0) { is64 = 0; break; }
        g_idx64 = is64;
    }
}

// -------------------- preprocessing kernels --------------------
__global__ void init_kernel() {
    int i = blockIdx.x * blockDim.x + threadIdx.x;
    int total = NV * HID;
    for (int idx = i; idx < total; idx += gridDim.x * blockDim.x) {
        g_h0[idx] = 0.0f;
        if (idx < NV) { g_deg[idx] = 0.0f; g_count[idx] = 0; }
    }
}

__global__ void deg_count_kernel(const void* __restrict__ ei,
                                 const float* __restrict__ ew) {
    int e = blockIdx.x * blockDim.x + threadIdx.x;
    if (e >= NE) return;
    int c = load_idx(ei, NE + e);
    atomicAdd(&g_deg[c], ew[e]);
    atomicAdd(&g_count[c], 1);
}

__global__ void dinv_kernel() {
    int n = blockIdx.x * blockDim.x + threadIdx.x;
    if (n >= NV) return;
    float d = rsqrtf(g_deg[n] + 1.0f);
    g_dinv[n]  = d;
    g_selfw[n] = d * d;
}

__global__ void norm_kernel(const void* __restrict__ ei,
                            const float* __restrict__ ew) {
    int e = blockIdx.x * blockDim.x + threadIdx.x;
    if (e >= NE) return;
    int r = load_idx(ei, e);
    int c = load_idx(ei, NE + e);
    g_norm[e] = g_dinv[r] * ew[e] * g_dinv[c];
}

__global__ void scan_kernel() {
    __shared__ int sh[1024];
    __shared__ int carry;
    if (threadIdx.x == 0) carry = 0;
    __syncthreads();
    for (int base = 0; base < NV; base += 1024) {
        int i = base + threadIdx.x;
        int v = (i < NV) ? g_count[i] : 0;
        sh[threadIdx.x] = v;
        __syncthreads();
        for (int off = 1; off < 1024; off <<= 1) {
            int t = (threadIdx.x >= off) ? sh[threadIdx.x - off] : 0;
            __syncthreads();
            sh[threadIdx.x] += t;
            __syncthreads();
        }
        if (i < NV) {
            int excl = carry + sh[threadIdx.x] - v;
            g_start[i] = excl;
            g_wptr[i]  = excl;
        }
        __syncthreads();
        if (threadIdx.x == 0) carry += sh[1023];
        __syncthreads();
    }
    if (threadIdx.x == 0) g_start[NV] = carry;
}

__global__ void fill_kernel(const void* __restrict__ ei) {
    int e = blockIdx.x * blockDim.x + threadIdx.x;
    if (e >= NE) return;
    int c = load_idx(ei, NE + e);
    int pos = atomicAdd(&g_wptr[c], 1);
    g_csr_src[pos] = load_idx(ei, e);
    g_csr_w[pos]   = g_norm[e];
}

// ==================== bf16 tensor-core GEMM with 3-term split ====================
// C[M,NC] = A[M,KK] * B.  BT=true: B is [NC,KK] row-major (used as B^T).
// Split each fp32 operand a = a_hi + a_lo (both bf16, ~17 mantissa bits total);
// C += Ahi*Bhi + Ahi*Blo + Alo*Bhi  (Alo*Blo ~2^-22 rel, dropped).
// Block tile 128x64, kTile 32. 8 warps as 2(M) x 4(N); warp tile 64x16.

#define BM 128
#define BN 64
#define KT 32
#define KPAD 40     // smem row length in bf16 elems (32 + 8 pad: conflict-free frags)

__device__ __forceinline__ void split2(float x, float y, uint32_t& hi, uint32_t& lo) {
    __nv_bfloat16 xh = __float2bfloat16(x);
    __nv_bfloat16 yh = __float2bfloat16(y);
    float xr = x - __bfloat162float(xh);
    float yr = y - __bfloat162float(yh);
    __nv_bfloat16 xl = __float2bfloat16(xr);
    __nv_bfloat16 yl = __float2bfloat16(yr);
    hi = ((uint32_t)__bfloat16_as_ushort(yh) << 16) | __bfloat16_as_ushort(xh);
    lo = ((uint32_t)__bfloat16_as_ushort(yl) << 16) | __bfloat16_as_ushort(xl);
}

__device__ __forceinline__ void mma_bf16(float c[4],
                                         uint32_t a0, uint32_t a1, uint32_t a2, uint32_t a3,
                                         uint32_t b0, uint32_t b1) {
    asm volatile(
        "mma.sync.aligned.m16n8k16.row.col.f32.bf16.bf16.f32 "
        "{%0,%1,%2,%3}, {%4,%5,%6,%7}, {%8,%9}, {%0,%1,%2,%3};"
        : "+f"(c[0]), "+f"(c[1]), "+f"(c[2]), "+f"(c[3])
        : "r"(a0), "r"(a1), "r"(a2), "r"(a3), "r"(b0), "r"(b1));
}

template <bool BT, int NC, int KK>
__device__ __forceinline__ void mma_gemm(const float* __restrict__ A,
                                         const float* __restrict__ B,
                                         float* __restrict__ C) {
    __shared__ __nv_bfloat16 Ah[BM][KPAD], Al[BM][KPAD];
    __shared__ __nv_bfloat16 Bh[BN][KPAD], Bl[BN][KPAD];

    int tid = threadIdx.x;
    int wid = tid >> 5, lane = tid & 31;
    int gid = lane >> 2, tig = lane & 3;       // mma group / thread-in-group
    int warp_m = wid & 1;                      // 2 M-groups of 64
    int warp_n = wid >> 1;                     // 4 N-groups of 16
    int row0 = blockIdx.y * BM;
    int col0 = blockIdx.x * BN;

    float c[4][2][4];                          // [m-frag][n-frag][regs]
    #pragma unroll
    for (int i = 0; i < 4; i++)
        #pragma unroll
        for (int j = 0; j < 2; j++)
            #pragma unroll
            for (int q = 0; q < 4; q++) c[i][j][q] = 0.0f;

    #pragma unroll 1
    for (int k0 = 0; k0 < KK; k0 += KT) {
        // ---- A tile: 128 x 32 fp32 -> bf16 hi/lo ----
        #pragma unroll
        for (int it = 0; it < 4; it++) {
            int r  = (tid >> 3) + it * 32;     // 0..127
            int kg = (tid & 7) * 4;            // 0,4,..,28
            float4 v = make_float4(0.f, 0.f, 0.f, 0.f);
            int gm = row0 + r;
            if (gm < NV)
                v = *reinterpret_cast<const float4*>(&A[(size_t)gm * KK + k0 + kg]);
            uint32_t h0, l0, h1, l1;
            split2(v.x, v.y, h0, l0);
            split2(v.z, v.w, h1, l1);
            *reinterpret_cast<uint32_t*>(&Ah[r][kg])     = h0;
            *reinterpret_cast<uint32_t*>(&Ah[r][kg + 2]) = h1;
            *reinterpret_cast<uint32_t*>(&Al[r][kg])     = l0;
            *reinterpret_cast<uint32_t*>(&Al[r][kg + 2]) = l1;
        }
        // ---- B tile: 64 x 32 (stored [n][k]) ----
        if (BT) {
            #pragma unroll
            for (int it = 0; it < 2; it++) {
                int n  = (tid >> 3) + it * 32; // 0..63
                int kg = (tid & 7) * 4;
                float4 v = *reinterpret_cast<const float4*>(
                    &B[(size_t)(col0 + n) * KK + k0 + kg]);
                uint32_t h0, l0, h1, l1;
                split2(v.x, v.y, h0, l0);
                split2(v.z, v.w, h1, l1);
                *reinterpret_cast<uint32_t*>(&Bh[n][kg])     = h0;
                *reinterpret_cast<uint32_t*>(&Bh[n][kg + 2]) = h1;
                *reinterpret_cast<uint32_t*>(&Bl[n][kg])     = l0;
                *reinterpret_cast<uint32_t*>(&Bl[n][kg + 2]) = l1;
            }
        } else {
            #pragma unroll
            for (int it = 0; it < 2; it++) {
                int k  = (tid >> 4) + it * 16; // 0..31
                int ng = (tid & 15) * 4;
                float4 v = *reinterpret_cast<const float4*>(
                    &B[(size_t)(k0 + k) * NC + col0 + ng]);
                float vv[4] = {v.x, v.y, v.z, v.w};
                #pragma unroll
                for (int q = 0; q < 4; q++) {
                    __nv_bfloat16 h = __float2bfloat16(vv[q]);
                    Bh[ng + q][k] = h;
                    Bl[ng + q][k] = __float2bfloat16(vv[q] - __bfloat162float(h));
                }
            }
        }
        __syncthreads();

        // ---- two m16n8k16 steps per stage ----
        #pragma unroll
        for (int kk = 0; kk < KT; kk += 16) {
            uint32_t ah[4][4], al[4][4], bh[2][2], bl[2][2];
            #pragma unroll
            for (int i = 0; i < 4; i++) {
                int m = warp_m * 64 + i * 16;
                ah[i][0] = *reinterpret_cast<uint32_t*>(&Ah[m + gid    ][kk + tig * 2]);
                ah[i][1] = *reinterpret_cast<uint32_t*>(&Ah[m + gid + 8][kk + tig * 2]);
                ah[i][2] = *reinterpret_cast<uint32_t*>(&Ah[m + gid    ][kk + tig * 2 + 8]);
                ah[i][3] = *reinterpret_cast<uint32_t*>(&Ah[m + gid + 8][kk + tig * 2 + 8]);
                al[i][0] = *reinterpret_cast<uint32_t*>(&Al[m + gid    ][kk + tig * 2]);
                al[i][1] = *reinterpret_cast<uint32_t*>(&Al[m + gid + 8][kk + tig * 2]);
                al[i][2] = *reinterpret_cast<uint32_t*>(&Al[m + gid    ][kk + tig * 2 + 8]);
                al[i][3] = *reinterpret_cast<uint32_t*>(&Al[m + gid + 8][kk + tig * 2 + 8]);
            }
            #pragma unroll
            for (int j = 0; j < 2; j++) {
                int n = warp_n * 16 + j * 8 + gid;
                bh[j][0] = *reinterpret_cast<uint32_t*>(&Bh[n][kk + tig * 2]);
                bh[j][1] = *reinterpret_cast<uint32_t*>(&Bh[n][kk + tig * 2 + 8]);
                bl[j][0] = *reinterpret_cast<uint32_t*>(&Bl[n][kk + tig * 2]);
                bl[j][1] = *reinterpret_cast<uint32_t*>(&Bl[n][kk + tig * 2 + 8]);
            }
            #pragma unroll
            for (int i = 0; i < 4; i++)
                #pragma unroll
                for (int j = 0; j < 2; j++) {
                    mma_bf16(c[i][j], ah[i][0], ah[i][1], ah[i][2], ah[i][3], bh[j][0], bh[j][1]);
                    mma_bf16(c[i][j], ah[i][0], ah[i][1], ah[i][2], ah[i][3], bl[j][0], bl[j][1]);
                    mma_bf16(c[i][j], al[i][0], al[i][1], al[i][2], al[i][3], bh[j][0], bh[j][1]);
                }
        }
        __syncthreads();
    }

    // ---- epilogue: store C ----
    #pragma unroll
    for (int i = 0; i < 4; i++) {
        int mA = row0 + warp_m * 64 + i * 16 + gid;
        int nA = col0 + warp_n * 16;
        #pragma unroll
        for (int j = 0; j < 2; j++) {
            int nc = nA + j * 8 + tig * 2;
            if (mA < NV)
                *reinterpret_cast<float2*>(&C[(size_t)mA * NC + nc]) =
                    make_float2(c[i][j][0], c[i][j][1]);
            if (mA + 8 < NV)
                *reinterpret_cast<float2*>(&C[(size_t)(mA + 8) * NC + nc]) =
                    make_float2(c[i][j][2], c[i][j][3]);
        }
    }
}

__global__ void __launch_bounds__(256, 2)
gemm_gi_kernel(const float* __restrict__ xs, const float* __restrict__ W_ih, int t) {
    mma_gemm<true, H3, DIN>(xs + (size_t)t * NV * DIN, W_ih, g_GI);
}

__global__ void __launch_bounds__(256, 2)
gemm_gh_kernel(const float* __restrict__ W_hh, int p) {
    mma_gemm<true, H3, HID>(hbuf(p), W_hh, g_GH);
}

__global__ void __launch_bounds__(256, 2)
gemm_cv_kernel(const float* __restrict__ conv_W, int l, int hp) {
    mma_gemm<false, HID, HID>(hbuf(hp), conv_W + (size_t)l * HID * HID, g_hW);
}

// -------------------- GRU pointwise: h_out = GRU(GI, GH, h_in) --------------------
__device__ __forceinline__ float sigm(float x) { return 1.0f / (1.0f + expf(-x)); }

__global__ void gru_kernel(const float* __restrict__ b_ih,
                           const float* __restrict__ b_hh, int p) {
    const float* h_in  = hbuf(p);
    float*       h_out = hbuf(p ^ 1);
    int idx = blockIdx.x * blockDim.x + threadIdx.x;   // NV*128 float4 lanes
    if (idx >= NV * 128) return;
    int n  = idx >> 7;
    int j4 = (idx & 127) * 4;
    size_t gbase = (size_t)n * H3 + j4;

    float4 ir  = *reinterpret_cast<const float4*>(&g_GI[gbase]);
    float4 iz  = *reinterpret_cast<const float4*>(&g_GI[gbase + HID]);
    float4 in_ = *reinterpret_cast<const float4*>(&g_GI[gbase + 2 * HID]);
    float4 hr  = *reinterpret_cast<const float4*>(&g_GH[gbase]);
    float4 hz  = *reinterpret_cast<const float4*>(&g_GH[gbase + HID]);
    float4 hn  = *reinterpret_cast<const float4*>(&g_GH[gbase + 2 * HID]);
    float4 bir = *reinterpret_cast<const float4*>(&b_ih[j4]);
    float4 biz = *reinterpret_cast<const float4*>(&b_ih[HID + j4]);
    float4 bin = *reinterpret_cast<const float4*>(&b_ih[2 * HID + j4]);
    float4 bhr = *reinterpret_cast<const float4*>(&b_hh[j4]);
    float4 bhz = *reinterpret_cast<const float4*>(&b_hh[HID + j4]);
    float4 bhn = *reinterpret_cast<const float4*>(&b_hh[2 * HID + j4]);
    float4 hv  = *reinterpret_cast<const float4*>(&h_in[(size_t)n * HID + j4]);

    float4 out;
    {
        float r = sigm(ir.x + bir.x + hr.x + bhr.x);
        float z = sigm(iz.x + biz.x + hz.x + bhz.x);
        float nn = tanhf(in_.x + bin.x + r * (hn.x + bhn.x));
        out.x = (1.0f - z) * nn + z * hv.x;
    }
    {
        float r = sigm(ir.y + bir.y + hr.y + bhr.y);
        float z = sigm(iz.y + biz.y + hz.y + bhz.y);
        float nn = tanhf(in_.y + bin.y + r * (hn.y + bhn.y));
        out.y = (1.0f - z) * nn + z * hv.y;
    }
    {
        float r = sigm(ir.z + bir.z + hr.z + bhr.z);
        float z = sigm(iz.z + biz.z + hz.z + bhz.z);
        float nn = tanhf(in_.z + bin.z + r * (hn.z + bhn.z));
        out.z = (1.0f - z) * nn + z * hv.z;
    }
    {
        float r = sigm(ir.w + bir.w + hr.w + bhr.w);
        float z = sigm(iz.w + biz.w + hz.w + bhz.w);
        float nn = tanhf(in_.w + bin.w + r * (hn.w + bhn.w));
        out.w = (1.0f - z) * nn + z * hv.w;
    }
    *reinterpret_cast<float4*>(&h_out[(size_t)n * HID + j4]) = out;
}

// -------------------- GCN aggregation: h = relu(agg + selfw*hW + b) --------------------
__global__ void agg_kernel(const float* __restrict__ conv_b, int l, int hp) {
    int n = blockIdx.x;
    int j = threadIdx.x;
    const float4* hw4 = reinterpret_cast<const float4*>(g_hW);
    const float*  bch = conv_b + (size_t)l * HID;
    float*        h   = hbuf(hp);

    float4 acc = make_float4(0.f, 0.f, 0.f, 0.f);
    int s = g_start[n], e = g_start[n + 1];
    for (int p = s; p < e; p++) {
        int   src = g_csr_src[p];
        float w   = g_csr_w[p];
        float4 v = __ldg(&hw4[(size_t)src * 128 + j]);
        acc.x = fmaf(w, v.x, acc.x);
        acc.y = fmaf(w, v.y, acc.y);
        acc.z = fmaf(w, v.z, acc.z);
        acc.w = fmaf(w, v.w, acc.w);
    }
    float sw = g_selfw[n];
    float4 hv = hw4[(size_t)n * 128 + j];
    float4 b  = reinterpret_cast<const float4*>(bch)[j];
    float4 r;
    r.x = fmaxf(acc.x + sw * hv.x + b.x, 0.0f);
    r.y = fmaxf(acc.y + sw * hv.y + b.y, 0.0f);
    r.z = fmaxf(acc.z + sw * hv.z + b.z, 0.0f);
    r.w = fmaxf(acc.w + sw * hv.w + b.w, 0.0f);
    reinterpret_cast<float4*>(h)[(size_t)n * 128 + j] = r;
}

// -------------------- final linear --------------------
__global__ void lin_kernel(const float* __restrict__ lin_W,
                           const float* __restrict__ lin_b,
                           float* __restrict__ out, int t, int hp) {
    const float* h = hbuf(hp);
    int warp = (blockIdx.x * blockDim.x + threadIdx.x) >> 5;
    int lane = threadIdx.x & 31;
    if (warp >= NV) return;
    float s = 0.0f;
    for (int j = lane; j < HID; j += 32)
        s = fmaf(h[(size_t)warp * HID + j], lin_W[j], s);
    #pragma unroll
    for (int o = 16; o > 0; o >>= 1) s += __shfl_down_sync(0xFFFFFFFFu, s, o);
    if (lane == 0) out[(size_t)t * NV + warp] = s + lin_b[0];
}

// -------------------- host orchestration: kernel launches ONLY --------------------
extern "C" void kernel_launch(void* const* d_in, const int* in_sizes, int n_in,
                              void* d_out, int out_size) {
    const float* xs     = (const float*)d_in[0];
    const void*  ei     = d_in[1];
    const float* ew     = (const float*)d_in[2];
    const float* W_ih   = (const float*)d_in[3];
    const float* W_hh   = (const float*)d_in[4];
    const float* b_ih   = (const float*)d_in[5];
    const float* b_hh   = (const float*)d_in[6];
    const float* conv_W = (const float*)d_in[7];
    const float* conv_b = (const float*)d_in[8];
    const float* lin_W  = (const float*)d_in[9];
    const float* lin_b  = (const float*)d_in[10];
    float* out = (float*)d_out;

    detect_kernel<<<1, 32>>>((const int*)ei);
    init_kernel<<<592, 256>>>();
    deg_count_kernel<<<(NE + 255) / 256, 256>>>(ei, ew);
    dinv_kernel<<<(NV + 255) / 256, 256>>>();
    norm_kernel<<<(NE + 255) / 256, 256>>>(ei, ew);
    scan_kernel<<<1, 1024>>>();
    fill_kernel<<<(NE + 255) / 256, 256>>>(ei);

    dim3 grid_gate(H3 / BN, (NV + BM - 1) / BM);   // 24 x 79
    dim3 grid_cv(HID / BN, (NV + BM - 1) / BM);    //  8 x 79
    int gru_blocks = (NV * 128 + 255) / 256;

    for (int t = 0; t < T_STEPS; t++) {
        int p = t & 1;   // h_in = hbuf(p); post-GRU state lives in hbuf(p^1)
        gemm_gi_kernel<<<grid_gate, 256>>>(xs, W_ih, t);
        gemm_gh_kernel<<<grid_gate, 256>>>(W_hh, p);
        gru_kernel<<<gru_blocks, 256>>>(b_ih, b_hh, p);
        for (int l = 0; l < NCONV; l++) {
            gemm_cv_kernel<<<grid_cv, 256>>>(conv_W, l, p ^ 1);
            agg_kernel<<<NV, 128>>>(conv_b, l, p ^ 1);
        }
        lin_kernel<<<(NV * 32 + 255) / 256, 256>>>(lin_W, lin_b, out, t, p ^ 1);
    }
}